// round 2
// baseline (speedup 1.0000x reference)
#include <cuda_runtime.h>

// QuantumEvolution: B=512 trajectories, M=2048 steps.
// U_t = exp(-i dt H_t), H = px*sx + py*sy + (0.5+nz)*sz (traceless) -> unit
// quaternion. Prefix product via: per-thread 8-step local prefixes ->
// warp shuffle scan -> warp-total composition (1 barrier total).

#define TPB    256
#define STEPS  8
#define MSTEPS 2048
#define BREAL  512

__device__ __forceinline__ float4 qmul(float4 a, float4 b) {
    // Hamilton product a*b; quaternion (w,x,y,z) stored in (x,y,z,w) fields.
    float4 r;
    r.x = a.x * b.x - a.y * b.y - a.z * b.z - a.w * b.w;
    r.y = a.x * b.y + a.y * b.x + a.z * b.w - a.w * b.z;
    r.z = a.x * b.z - a.y * b.w + a.z * b.x + a.w * b.y;
    r.w = a.x * b.w + a.y * b.z - a.z * b.y + a.w * b.x;
    return r;
}

__device__ __forceinline__ float4 shfl_up_q(float4 v, int off) {
    float4 r;
    r.x = __shfl_up_sync(0xFFFFFFFFu, v.x, off);
    r.y = __shfl_up_sync(0xFFFFFFFFu, v.y, off);
    r.z = __shfl_up_sync(0xFFFFFFFFu, v.z, off);
    r.w = __shfl_up_sync(0xFFFFFFFFu, v.w, off);
    return r;
}

__global__ __launch_bounds__(TPB)
void qe_kernel(const float* __restrict__ noise,
               const float* __restrict__ pulses,
               float* __restrict__ out) {
    const int b    = blockIdx.x;
    const int tid  = threadIdx.x;
    const int lane = tid & 31;
    const int wid  = tid >> 5;
    const float dt = 1.0f / 2048.0f;
    const int t0 = tid * STEPS;

    // Coalesced vector loads: each thread owns 8 consecutive time steps.
    const float4* p4 = reinterpret_cast<const float4*>(pulses + (size_t)b * MSTEPS * 2 + t0 * 2);
    const float4* n4 = reinterpret_cast<const float4*>(noise  + (size_t)b * MSTEPS     + t0);
    float4 pa = p4[0], pb = p4[1], pc = p4[2], pd = p4[3];
    float4 na = n4[0], nb = n4[1];

    float px[STEPS] = {pa.x, pa.z, pb.x, pb.z, pc.x, pc.z, pd.x, pd.z};
    float py[STEPS] = {pa.y, pa.w, pb.y, pb.w, pc.y, pc.w, pd.y, pd.w};
    float nz[STEPS] = {na.x, na.y, na.z, na.w, nb.x, nb.y, nb.z, nb.w};

    // Local inclusive quaternion prefixes (newer step multiplies on the left).
    float4 L[STEPS];
    float4 q = make_float4(1.f, 0.f, 0.f, 0.f);
#pragma unroll
    for (int i = 0; i < STEPS; i++) {
        float hx = px[i], hy = py[i], hz = 0.5f + nz[i];
        float t2 = (dt * dt) * (hx * hx + hy * hy + hz * hz);   // theta^2 <= ~1.5e-5
        float c = 1.f - t2 * (0.5f - t2 * (1.f / 24.f));        // cos(theta)
        float k = dt * (1.f - t2 * ((1.f / 6.f) - t2 * (1.f / 120.f)));  // dt*sinc
        float4 u = make_float4(c, k * hx, k * hy, k * hz);
        q = qmul(u, q);
        L[i] = q;
    }

    // Warp-level inclusive scan of per-thread chunk products (shuffle, no smem).
    float4 v = q;
#pragma unroll
    for (int off = 1; off < 32; off <<= 1) {
        float4 o = shfl_up_q(v, off);
        if (lane >= off) v = qmul(v, o);   // newer range on the left
    }

    // Publish warp totals; single block barrier.
    __shared__ float4 wtot[TPB / 32];
    if (lane == 31) wtot[wid] = v;
    __syncthreads();

    // Warp-exclusive prefix: compose totals of warps [0, wid). Uniform per warp.
    float4 WE = make_float4(1.f, 0.f, 0.f, 0.f);
    for (int w = 0; w < wid; w++) WE = qmul(wtot[w], WE);

    // Thread-exclusive prefix within warp.
    float4 TE = shfl_up_q(v, 1);
    if (lane == 0) TE = make_float4(1.f, 0.f, 0.f, 0.f);

    float4 E = qmul(TE, WE);   // exclusive global prefix for this thread's chunk

    // Compose global prefixes and emit 6 expectation values per step.
    float obuf[STEPS * 6];
#pragma unroll
    for (int i = 0; i < STEPS; i++) {
        float4 P = qmul(L[i], E);
        float w = P.x, x = P.y, y = P.z, z = P.w;
        obuf[i * 6 + 0] = 2.f * (x * z + w * y);          // rho0, sx
        obuf[i * 6 + 1] = 2.f * (y * z - w * x);          // rho0, sy
        obuf[i * 6 + 2] = 1.f - 2.f * (x * x + y * y);    // rho0, sz
        obuf[i * 6 + 3] = 1.f - 2.f * (y * y + z * z);    // rho1, sx
        obuf[i * 6 + 4] = 2.f * (x * y + w * z);          // rho1, sy
        obuf[i * 6 + 5] = 2.f * (x * z - w * y);          // rho1, sz
    }

    // 48 contiguous floats per thread -> 12 aligned float4 stores.
    float4* o4 = reinterpret_cast<float4*>(out + ((size_t)b * MSTEPS + t0) * 6);
#pragma unroll
    for (int j = 0; j < 12; j++) o4[j] = reinterpret_cast<const float4*>(obuf)[j];
}

extern "C" void kernel_launch(void* const* d_in, const int* in_sizes, int n_in,
                              void* d_out, int out_size) {
    const float* noise  = (const float*)d_in[0];   // [512, 2048, 1]
    const float* pulses = (const float*)d_in[1];   // [512, 2048, 2]
    if (in_sizes[0] > in_sizes[1]) {               // defensive: order by size
        const float* t = noise; noise = pulses; pulses = t;
    }
    qe_kernel<<<BREAL, TPB>>>(noise, pulses, (float*)d_out);
}

// round 3
// speedup vs baseline: 1.0193x; 1.0193x over previous
#include <cuda_runtime.h>

// QuantumEvolution: B=512 trajectories, M=2048 steps.
// U_t = exp(-i dt H_t), H traceless -> unit quaternion; prefix product via
// warp shuffle scan + one block barrier. This revision eliminates register
// spills: no obuf[48], no L[8]; step quaternions are recomputed in the
// epilogue from the (already live) input registers.

#define TPB    256
#define STEPS  8
#define MSTEPS 2048
#define BREAL  512

__device__ __forceinline__ float4 qmul(float4 a, float4 b) {
    // Hamilton product a*b; quaternion (w,x,y,z) in (x,y,z,w) fields.
    float4 r;
    r.x = a.x * b.x - a.y * b.y - a.z * b.z - a.w * b.w;
    r.y = a.x * b.y + a.y * b.x + a.z * b.w - a.w * b.z;
    r.z = a.x * b.z - a.y * b.w + a.z * b.x + a.w * b.y;
    r.w = a.x * b.w + a.y * b.z - a.z * b.y + a.w * b.x;
    return r;
}

__device__ __forceinline__ float4 shfl_up_q(float4 v, int off) {
    float4 r;
    r.x = __shfl_up_sync(0xFFFFFFFFu, v.x, off);
    r.y = __shfl_up_sync(0xFFFFFFFFu, v.y, off);
    r.z = __shfl_up_sync(0xFFFFFFFFu, v.z, off);
    r.w = __shfl_up_sync(0xFFFFFFFFu, v.w, off);
    return r;
}

// Step quaternion u = exp(-i dt H) for H = hx*sx + hy*sy + hz*sz.
__device__ __forceinline__ float4 stepq(float hx, float hy, float hz) {
    const float dt = 1.0f / 2048.0f;
    float t2 = (dt * dt) * (hx * hx + hy * hy + hz * hz);   // theta^2 <= ~1.5e-5
    float c = 1.f - t2 * (0.5f - t2 * (1.f / 24.f));        // cos(theta)
    float k = dt * (1.f - t2 * ((1.f / 6.f) - t2 * (1.f / 120.f)));  // dt*sinc
    return make_float4(c, k * hx, k * hy, k * hz);
}

__global__ __launch_bounds__(TPB, 4)
void qe_kernel(const float* __restrict__ noise,
               const float* __restrict__ pulses,
               float* __restrict__ out) {
    const int b    = blockIdx.x;
    const int tid  = threadIdx.x;
    const int lane = tid & 31;
    const int wid  = tid >> 5;
    const int t0   = tid * STEPS;

    // Coalesced vector loads: each thread owns 8 consecutive time steps.
    const float4* p4 = reinterpret_cast<const float4*>(pulses + (size_t)b * MSTEPS * 2 + t0 * 2);
    const float4* n4 = reinterpret_cast<const float4*>(noise  + (size_t)b * MSTEPS     + t0);
    const float4 pa = p4[0], pb = p4[1], pc = p4[2], pd = p4[3];
    const float4 na = n4[0], nb = n4[1];

    // Chunk product of the 8 step quaternions (newer on the left). No L[] kept.
    float4 q = stepq(pa.x, pa.y, 0.5f + na.x);
    q = qmul(stepq(pa.z, pa.w, 0.5f + na.y), q);
    q = qmul(stepq(pb.x, pb.y, 0.5f + na.z), q);
    q = qmul(stepq(pb.z, pb.w, 0.5f + na.w), q);
    q = qmul(stepq(pc.x, pc.y, 0.5f + nb.x), q);
    q = qmul(stepq(pc.z, pc.w, 0.5f + nb.y), q);
    q = qmul(stepq(pd.x, pd.y, 0.5f + nb.z), q);
    q = qmul(stepq(pd.z, pd.w, 0.5f + nb.w), q);

    // Warp-level inclusive scan of chunk products (shuffle, no smem).
    float4 v = q;
#pragma unroll
    for (int off = 1; off < 32; off <<= 1) {
        float4 o = shfl_up_q(v, off);
        if (lane >= off) v = qmul(v, o);
    }

    // Publish warp totals; single block barrier.
    __shared__ float4 wtot[TPB / 32];
    if (lane == 31) wtot[wid] = v;
    __syncthreads();

    // Warp-exclusive prefix (uniform per warp).
    float4 WE = make_float4(1.f, 0.f, 0.f, 0.f);
    for (int w = 0; w < wid; w++) WE = qmul(wtot[w], WE);

    // Thread-exclusive prefix within warp.
    float4 TE = shfl_up_q(v, 1);
    if (lane == 0) TE = make_float4(1.f, 0.f, 0.f, 0.f);

    float4 P = qmul(TE, WE);   // running global prefix (exclusive at entry)

    // Epilogue: recompute step quaternions, advance P, emit 6 values/step.
    // 2 steps per group -> 12 named scalars -> 3 float4 stores. No arrays.
    float4* o4 = reinterpret_cast<float4*>(out + ((size_t)b * MSTEPS + t0) * 6);

#pragma unroll
    for (int g = 0; g < 4; g++) {
        float hx0, hy0, hz0, hx1, hy1, hz1;
        if (g == 0) { hx0 = pa.x; hy0 = pa.y; hz0 = 0.5f + na.x;
                      hx1 = pa.z; hy1 = pa.w; hz1 = 0.5f + na.y; }
        else if (g == 1) { hx0 = pb.x; hy0 = pb.y; hz0 = 0.5f + na.z;
                           hx1 = pb.z; hy1 = pb.w; hz1 = 0.5f + na.w; }
        else if (g == 2) { hx0 = pc.x; hy0 = pc.y; hz0 = 0.5f + nb.x;
                           hx1 = pc.z; hy1 = pc.w; hz1 = 0.5f + nb.y; }
        else             { hx0 = pd.x; hy0 = pd.y; hz0 = 0.5f + nb.z;
                           hx1 = pd.z; hy1 = pd.w; hz1 = 0.5f + nb.w; }

        P = qmul(stepq(hx0, hy0, hz0), P);
        float w0 = P.x, x0 = P.y, y0 = P.z, z0 = P.w;
        float s0 = 2.f * (x0 * z0 + w0 * y0);          // rho0, sx
        float s1 = 2.f * (y0 * z0 - w0 * x0);          // rho0, sy
        float s2 = 1.f - 2.f * (x0 * x0 + y0 * y0);    // rho0, sz
        float s3 = 1.f - 2.f * (y0 * y0 + z0 * z0);    // rho1, sx
        float s4 = 2.f * (x0 * y0 + w0 * z0);          // rho1, sy
        float s5 = 2.f * (x0 * z0 - w0 * y0);          // rho1, sz

        P = qmul(stepq(hx1, hy1, hz1), P);
        float w1 = P.x, x1 = P.y, y1 = P.z, z1 = P.w;
        float s6  = 2.f * (x1 * z1 + w1 * y1);
        float s7  = 2.f * (y1 * z1 - w1 * x1);
        float s8  = 1.f - 2.f * (x1 * x1 + y1 * y1);
        float s9  = 1.f - 2.f * (y1 * y1 + z1 * z1);
        float s10 = 2.f * (x1 * y1 + w1 * z1);
        float s11 = 2.f * (x1 * z1 - w1 * y1);

        o4[g * 3 + 0] = make_float4(s0, s1, s2, s3);
        o4[g * 3 + 1] = make_float4(s4, s5, s6, s7);
        o4[g * 3 + 2] = make_float4(s8, s9, s10, s11);
    }
}

extern "C" void kernel_launch(void* const* d_in, const int* in_sizes, int n_in,
                              void* d_out, int out_size) {
    const float* noise  = (const float*)d_in[0];   // [512, 2048, 1]
    const float* pulses = (const float*)d_in[1];   // [512, 2048, 2]
    if (in_sizes[0] > in_sizes[1]) {               // defensive: order by size
        const float* t = noise; noise = pulses; pulses = t;
    }
    qe_kernel<<<BREAL, TPB>>>(noise, pulses, (float*)d_out);
}

// round 4
// speedup vs baseline: 1.2948x; 1.2703x over previous
#include <cuda_runtime.h>

// QuantumEvolution: B=512 x M=2048, SU(2) propagators as unit quaternions,
// prefix product via warp shuffle scan + 1 block barrier.
// This revision fixes L1 wavefront inflation: all global loads/stores are
// fully coalesced; per-thread (strided) access happens only in padded smem.

#define TPB    256
#define MSTEPS 2048
#define BREAL  512

// smem float buffer (reused):
//   load phase : pulses rows [0, 256*17)  +  noise rows [256*17, 256*17+256*9)
//   store phase: stage rows  [0, 128*49)
#define SM_P_OFF   0
#define SM_N_OFF   (256 * 17)
#define SM_FLOATS  (256 * 17 + 256 * 9)   // 6656 floats = 26.6 KB

__device__ __forceinline__ float4 qmul(float4 a, float4 b) {
    float4 r;
    r.x = a.x * b.x - a.y * b.y - a.z * b.z - a.w * b.w;
    r.y = a.x * b.y + a.y * b.x + a.z * b.w - a.w * b.z;
    r.z = a.x * b.z - a.y * b.w + a.z * b.x + a.w * b.y;
    r.w = a.x * b.w + a.y * b.z - a.z * b.y + a.w * b.x;
    return r;
}

__device__ __forceinline__ float4 shfl_up_q(float4 v, int off) {
    float4 r;
    r.x = __shfl_up_sync(0xFFFFFFFFu, v.x, off);
    r.y = __shfl_up_sync(0xFFFFFFFFu, v.y, off);
    r.z = __shfl_up_sync(0xFFFFFFFFu, v.z, off);
    r.w = __shfl_up_sync(0xFFFFFFFFu, v.w, off);
    return r;
}

__device__ __forceinline__ float4 stepq(float hx, float hy, float hz) {
    const float dt = 1.0f / 2048.0f;
    float t2 = (dt * dt) * (hx * hx + hy * hy + hz * hz);   // theta^2 <= ~1.5e-5
    float c = 1.f - t2 * (0.5f - t2 * (1.f / 24.f));        // cos(theta)
    float k = dt * (1.f - t2 * ((1.f / 6.f) - t2 * (1.f / 120.f)));  // dt*sinc
    return make_float4(c, k * hx, k * hy, k * hz);
}

__global__ __launch_bounds__(TPB, 4)
void qe_kernel(const float* __restrict__ noise,
               const float* __restrict__ pulses,
               float* __restrict__ out) {
    __shared__ float  sm[SM_FLOATS];
    __shared__ float4 wtot[TPB / 32];

    const int b    = blockIdx.x;
    const int tid  = threadIdx.x;
    const int lane = tid & 31;
    const int wid  = tid >> 5;

    // ---- Coalesced cooperative load: gmem -> padded smem rows ----
    // pulses: 4096 floats/block. Row t holds thread t's 16 floats, pad to 17.
    const float4* gp = reinterpret_cast<const float4*>(pulses + (size_t)b * MSTEPS * 2);
#pragma unroll
    for (int k = 0; k < 4; k++) {
        int g = tid + 256 * k;                 // float4 index
        float4 v = gp[g];
        int row = g >> 2, col = (g & 3) * 4;   // logical float 4g -> (row,col)
        float* d = &sm[SM_P_OFF + row * 17 + col];
        d[0] = v.x; d[1] = v.y; d[2] = v.z; d[3] = v.w;
    }
    // noise: 2048 floats/block. Row t holds thread t's 8 floats, pad to 9.
    const float4* gn = reinterpret_cast<const float4*>(noise + (size_t)b * MSTEPS);
#pragma unroll
    for (int k = 0; k < 2; k++) {
        int g = tid + 256 * k;
        float4 v = gn[g];
        int row = g >> 1, col = (g & 1) * 4;
        float* d = &sm[SM_N_OFF + row * 9 + col];
        d[0] = v.x; d[1] = v.y; d[2] = v.z; d[3] = v.w;
    }
    __syncthreads();

    // ---- Per-thread inputs (conflict-free: gcd(17,32)=gcd(9,32)=1) ----
    float px[8], py[8], nz[8];
#pragma unroll
    for (int i = 0; i < 8; i++) {
        px[i] = sm[SM_P_OFF + tid * 17 + 2 * i];
        py[i] = sm[SM_P_OFF + tid * 17 + 2 * i + 1];
        nz[i] = 0.5f + sm[SM_N_OFF + tid * 9 + i];
    }

    // ---- Chunk product of 8 step quaternions (newer on the left) ----
    float4 q = stepq(px[0], py[0], nz[0]);
#pragma unroll
    for (int i = 1; i < 8; i++) q = qmul(stepq(px[i], py[i], nz[i]), q);

    // ---- Warp-level inclusive scan of chunk products ----
    float4 v = q;
#pragma unroll
    for (int off = 1; off < 32; off <<= 1) {
        float4 o = shfl_up_q(v, off);
        if (lane >= off) v = qmul(v, o);
    }

    if (lane == 31) wtot[wid] = v;
    __syncthreads();                 // also: all smem input reads are done

    float4 WE = make_float4(1.f, 0.f, 0.f, 0.f);
    for (int w = 0; w < wid; w++) WE = qmul(wtot[w], WE);

    float4 TE = shfl_up_q(v, 1);
    if (lane == 0) TE = make_float4(1.f, 0.f, 0.f, 0.f);

    const float4 E = qmul(TE, WE);   // exclusive global prefix for this chunk

    // ---- Epilogue in two 128-thread halves, staged through smem ----
    float* outb = out + (size_t)b * (MSTEPS * 6);
#pragma unroll
    for (int h = 0; h < 2; h++) {
        if ((tid >> 7) == h) {
            int t = tid & 127;                 // stage row, pad 49 (gcd(49,32)=1)
            float4 P = E;
#pragma unroll
            for (int i = 0; i < 8; i++) {
                P = qmul(stepq(px[i], py[i], nz[i]), P);
                float w = P.x, x = P.y, y = P.z, z = P.w;
                float* d = &sm[t * 49 + i * 6];
                d[0] = 2.f * (x * z + w * y);          // rho0, sx
                d[1] = 2.f * (y * z - w * x);          // rho0, sy
                d[2] = 1.f - 2.f * (x * x + y * y);    // rho0, sz
                d[3] = 1.f - 2.f * (y * y + z * z);    // rho1, sx
                d[4] = 2.f * (x * y + w * z);          // rho1, sy
                d[5] = 2.f * (x * z - w * y);          // rho1, sz
            }
        }
        __syncthreads();
        // Coalesced copy-out of this half's 6144 contiguous floats.
        float4* og = reinterpret_cast<float4*>(outb + h * 6144);
#pragma unroll
        for (int k = 0; k < 6; k++) {
            int g = tid + 256 * k;             // float4 index within half
            int row = g / 12;                  // stage row
            int col = 4 * g - row * 48;        // float col within row
            const float* s = &sm[row * 49 + col];
            og[g] = make_float4(s[0], s[1], s[2], s[3]);
        }
        if (h == 0) __syncthreads();           // protect stage before half 2
    }
}

extern "C" void kernel_launch(void* const* d_in, const int* in_sizes, int n_in,
                              void* d_out, int out_size) {
    const float* noise  = (const float*)d_in[0];   // [512, 2048, 1]
    const float* pulses = (const float*)d_in[1];   // [512, 2048, 2]
    if (in_sizes[0] > in_sizes[1]) {               // defensive: order by size
        const float* t = noise; noise = pulses; pulses = t;
    }
    qe_kernel<<<BREAL, TPB>>>(noise, pulses, (float*)d_out);
}